// round 1
// baseline (speedup 1.0000x reference)
#include <cuda_runtime.h>

// VectorQuantizer: latents [B=64, D=64, H=32, W=32] f32, codebook [K=1024, D=64] f32.
// Output: quantized latents [B, D, H, W] (= codebook[argmin dist]) followed by
// scalar vq_loss = 1.25 * mean((q - x)^2)  at out[B*D*H*W].
//
// Round 1 strategy: fp32 FFMA distance kernel.
//   dist_k = ||x||^2 + ||c_k||^2 - 2 x.c_k ; argmin over k only needs
//   score_k = ||c_k||^2 - 2 x.c_k  (||x||^2 constant per position).
// Each thread owns one position: 64 x-values in registers, codebook streamed
// through shared memory in 128-code tiles. 4 independent accumulators for ILP.
// ||c_k||^2 precomputed once per launch by a tiny kernel (codebook is an input).
// Loss: per-thread min-dist -> deterministic block tree reduction -> per-block
// partial -> deterministic single-block final reduction.

#define DIMS   64
#define KCODES 1024
#define HW     1024     // 32*32
#define TILE   128
#define THREADS 128
#define NPOS   65536    // 64 * 32 * 32
#define NBLOCKS (NPOS / THREADS)  // 512

__device__ float g_cnorm[KCODES];
__device__ float g_partial[NBLOCKS];

// ---------------------------------------------------------------------------
// ||c_k||^2 for every code
// ---------------------------------------------------------------------------
__global__ void cnorm_kernel(const float* __restrict__ cb) {
    int k = blockIdx.x * blockDim.x + threadIdx.x;
    if (k < KCODES) {
        const float4* c = reinterpret_cast<const float4*>(cb + k * DIMS);
        float s0 = 0.f, s1 = 0.f, s2 = 0.f, s3 = 0.f;
        #pragma unroll
        for (int i = 0; i < DIMS / 4; ++i) {
            float4 v = c[i];
            s0 = fmaf(v.x, v.x, s0);
            s1 = fmaf(v.y, v.y, s1);
            s2 = fmaf(v.z, v.z, s2);
            s3 = fmaf(v.w, v.w, s3);
        }
        g_cnorm[k] = (s0 + s1) + (s2 + s3);
    }
}

// ---------------------------------------------------------------------------
// Main: per-position argmin + gather + per-block loss partial
// ---------------------------------------------------------------------------
__global__ __launch_bounds__(THREADS, 4) void vq_kernel(
    const float* __restrict__ latents,
    const float* __restrict__ cb,
    float* __restrict__ out)
{
    __shared__ float sC[TILE * DIMS];   // 32 KB codebook tile
    __shared__ float sCn[TILE];
    __shared__ float sRed[THREADS];

    const int p  = blockIdx.x * THREADS + threadIdx.x;  // position id, < 65536
    const int b  = p >> 10;          // batch
    const int hw = p & (HW - 1);     // spatial index

    // Load this position's D=64 vector (stride HW between d's; coalesced across
    // threads since consecutive threads have consecutive hw).
    const float* xin = latents + (size_t)b * (DIMS * HW) + hw;
    float x[DIMS];
    float xn0 = 0.f, xn1 = 0.f, xn2 = 0.f, xn3 = 0.f;
    #pragma unroll
    for (int d = 0; d < DIMS; d += 4) {
        x[d + 0] = xin[(d + 0) * HW];
        x[d + 1] = xin[(d + 1) * HW];
        x[d + 2] = xin[(d + 2) * HW];
        x[d + 3] = xin[(d + 3) * HW];
        xn0 = fmaf(x[d + 0], x[d + 0], xn0);
        xn1 = fmaf(x[d + 1], x[d + 1], xn1);
        xn2 = fmaf(x[d + 2], x[d + 2], xn2);
        xn3 = fmaf(x[d + 3], x[d + 3], xn3);
    }
    const float xnorm = (xn0 + xn1) + (xn2 + xn3);

    float best = 3.402823466e38f;
    int   bidx = 0;

    for (int t = 0; t < KCODES; t += TILE) {
        __syncthreads();   // protect previous tile's readers
        // Cooperative tile load: TILE*DIMS floats = 2048 float4.
        {
            const float4* src = reinterpret_cast<const float4*>(cb + t * DIMS);
            float4* dst = reinterpret_cast<float4*>(sC);
            #pragma unroll
            for (int i = threadIdx.x; i < TILE * DIMS / 4; i += THREADS)
                dst[i] = src[i];
            if (threadIdx.x < TILE) sCn[threadIdx.x] = g_cnorm[t + threadIdx.x];
        }
        __syncthreads();

        for (int k = 0; k < TILE; ++k) {
            const float* c = &sC[k * DIMS];
            float a0 = 0.f, a1 = 0.f, a2 = 0.f, a3 = 0.f;
            #pragma unroll
            for (int d = 0; d < DIMS; d += 4) {
                a0 = fmaf(x[d + 0], c[d + 0], a0);
                a1 = fmaf(x[d + 1], c[d + 1], a1);
                a2 = fmaf(x[d + 2], c[d + 2], a2);
                a3 = fmaf(x[d + 3], c[d + 3], a3);
            }
            const float dot = (a0 + a1) + (a2 + a3);
            const float score = fmaf(-2.f, dot, sCn[k]);
            if (score < best) { best = score; bidx = t + k; }  // strict <: first index on ties
        }
    }

    // Gather selected code row (float4 from L2) and scatter into [B,D,H,W].
    {
        const float4* c = reinterpret_cast<const float4*>(cb + bidx * DIMS);
        float* o = out + (size_t)b * (DIMS * HW) + hw;
        #pragma unroll
        for (int i = 0; i < DIMS / 4; ++i) {
            float4 v = c[i];
            o[(4 * i + 0) * HW] = v.x;
            o[(4 * i + 1) * HW] = v.y;
            o[(4 * i + 2) * HW] = v.z;
            o[(4 * i + 3) * HW] = v.w;
        }
    }

    // Per-thread min distance = ||x||^2 + score; deterministic block reduce.
    sRed[threadIdx.x] = xnorm + best;
    __syncthreads();
    #pragma unroll
    for (int s = THREADS / 2; s > 0; s >>= 1) {
        if (threadIdx.x < s) sRed[threadIdx.x] += sRed[threadIdx.x + s];
        __syncthreads();
    }
    if (threadIdx.x == 0) g_partial[blockIdx.x] = sRed[0];
}

// ---------------------------------------------------------------------------
// Final deterministic loss reduction: out[ndhw] = 1.25 * sum / (N*D)
// ---------------------------------------------------------------------------
__global__ void loss_kernel(float* __restrict__ out, int ndhw) {
    __shared__ float red[NBLOCKS];
    red[threadIdx.x] = g_partial[threadIdx.x];
    __syncthreads();
    #pragma unroll
    for (int s = NBLOCKS / 2; s > 0; s >>= 1) {
        if (threadIdx.x < s) red[threadIdx.x] += red[threadIdx.x + s];
        __syncthreads();
    }
    if (threadIdx.x == 0)
        out[ndhw] = 1.25f * red[0] / (float)ndhw;  // mean over B*H*W*D elements
}

// ---------------------------------------------------------------------------
extern "C" void kernel_launch(void* const* d_in, const int* in_sizes, int n_in,
                              void* d_out, int out_size) {
    const float* latents = (const float*)d_in[0];  // [64,64,32,32] = 4194304
    const float* cb      = (const float*)d_in[1];  // [1024,64]     = 65536
    float* out = (float*)d_out;                    // 4194304 quantized + 1 loss
    const int ndhw = in_sizes[0];                  // 4194304

    cnorm_kernel<<<(KCODES + 255) / 256, 256>>>(cb);
    vq_kernel<<<NBLOCKS, THREADS>>>(latents, cb, out);
    loss_kernel<<<1, NBLOCKS>>>(out, ndhw);
}

// round 2
// speedup vs baseline: 1.0768x; 1.0768x over previous
#include <cuda_runtime.h>

// VectorQuantizer: latents [B=64, D=64, H=32, W=32] f32, codebook [K=1024, D=64] f32.
// Output: quantized latents [B, D, H, W] (= codebook[argmin dist]) followed by
// scalar vq_loss = 1.25 * mean((q - x)^2)  at out[B*D*H*W].
//
// Round 2: packed fp32 (fma.rn.f32x2 / SASS FFMA2) distance kernel — 2 fp32
// FMAs per lane per instruction on sm_103a, exact fp32 arithmetic.
//   score_k = ||c_k||^2 - 2 x.c_k   (argmin unaffected by dropping ||x||^2)
// Per-thread: one position, 64 dims packed into 32 f32x2 registers; codebook
// streamed through shared memory in 128-code tiles, read as ulonglong2 (LDS.128).

#define DIMS    64
#define KCODES  1024
#define HW      1024     // 32*32
#define TILE    128
#define THREADS 128
#define NPOS    65536    // 64 * 32 * 32
#define NBLOCKS (NPOS / THREADS)  // 512

// packed f32x2 helpers (Blackwell sm_103a)
#define FMA2(acc, xx, cc) \
    asm("fma.rn.f32x2 %0, %1, %2, %0;" : "+l"(acc) : "l"(xx), "l"(cc))
#define ADD2(d, a, b) \
    asm("add.rn.f32x2 %0, %1, %2;" : "=l"(d) : "l"(a), "l"(b))
#define PACK2(d, lo, hi) \
    asm("mov.b64 %0, {%1, %2};" : "=l"(d) : "f"(lo), "f"(hi))
#define UNPACK2(lo, hi, s) \
    asm("mov.b64 {%0, %1}, %2;" : "=f"(lo), "=f"(hi) : "l"(s))

__device__ float g_cnorm[KCODES];
__device__ float g_partial[NBLOCKS];

// ---------------------------------------------------------------------------
// ||c_k||^2 for every code
// ---------------------------------------------------------------------------
__global__ void cnorm_kernel(const float* __restrict__ cb) {
    int k = blockIdx.x * blockDim.x + threadIdx.x;
    if (k < KCODES) {
        const float4* c = reinterpret_cast<const float4*>(cb + k * DIMS);
        float s0 = 0.f, s1 = 0.f, s2 = 0.f, s3 = 0.f;
        #pragma unroll
        for (int i = 0; i < DIMS / 4; ++i) {
            float4 v = c[i];
            s0 = fmaf(v.x, v.x, s0);
            s1 = fmaf(v.y, v.y, s1);
            s2 = fmaf(v.z, v.z, s2);
            s3 = fmaf(v.w, v.w, s3);
        }
        g_cnorm[k] = (s0 + s1) + (s2 + s3);
    }
}

// ---------------------------------------------------------------------------
// Main: per-position argmin + gather + per-block loss partial
// ---------------------------------------------------------------------------
__global__ __launch_bounds__(THREADS, 4) void vq_kernel(
    const float* __restrict__ latents,
    const float* __restrict__ cb,
    float* __restrict__ out)
{
    __shared__ float sC[TILE * DIMS];   // 32 KB codebook tile
    __shared__ float sCn[TILE];
    __shared__ float sRed[THREADS];

    const int p  = blockIdx.x * THREADS + threadIdx.x;  // position id, < 65536
    const int b  = p >> 10;          // batch
    const int hw = p & (HW - 1);     // spatial index

    // Load this position's D=64 vector (stride HW between d's; coalesced across
    // threads since consecutive threads have consecutive hw). Pack into f32x2.
    const float* xin = latents + (size_t)b * (DIMS * HW) + hw;
    unsigned long long x2[DIMS / 2];
    float xn0 = 0.f, xn1 = 0.f;
    #pragma unroll
    for (int d = 0; d < DIMS; d += 2) {
        float v0 = xin[(d + 0) * HW];
        float v1 = xin[(d + 1) * HW];
        xn0 = fmaf(v0, v0, xn0);
        xn1 = fmaf(v1, v1, xn1);
        PACK2(x2[d / 2], v0, v1);
    }
    const float xnorm = xn0 + xn1;

    float best = 3.402823466e38f;
    int   bidx = 0;

    for (int t = 0; t < KCODES; t += TILE) {
        __syncthreads();   // protect previous tile's readers
        // Cooperative tile load: TILE*DIMS floats = 2048 float4.
        {
            const float4* src = reinterpret_cast<const float4*>(cb + t * DIMS);
            float4* dst = reinterpret_cast<float4*>(sC);
            #pragma unroll
            for (int i = threadIdx.x; i < TILE * DIMS / 4; i += THREADS)
                dst[i] = src[i];
            if (threadIdx.x < TILE) sCn[threadIdx.x] = g_cnorm[t + threadIdx.x];
        }
        __syncthreads();

        #pragma unroll 2
        for (int k = 0; k < TILE; ++k) {
            const ulonglong2* c2 =
                reinterpret_cast<const ulonglong2*>(sC + k * DIMS);  // 16 elems
            unsigned long long a0 = 0ull, a1 = 0ull, a2 = 0ull, a3 = 0ull;
            #pragma unroll
            for (int i = 0; i < 16; i += 2) {
                ulonglong2 v0 = c2[i];      // dims 4i   .. 4i+3 (2 packed pairs)
                ulonglong2 v1 = c2[i + 1];  // dims 4i+4 .. 4i+7
                FMA2(a0, x2[2 * i + 0], v0.x);
                FMA2(a1, x2[2 * i + 1], v0.y);
                FMA2(a2, x2[2 * i + 2], v1.x);
                FMA2(a3, x2[2 * i + 3], v1.y);
            }
            ADD2(a0, a0, a1);
            ADD2(a2, a2, a3);
            ADD2(a0, a0, a2);
            float lo, hi;
            UNPACK2(lo, hi, a0);
            const float dot = lo + hi;
            const float score = fmaf(-2.f, dot, sCn[k]);
            if (score < best) { best = score; bidx = t + k; }  // strict <: first index wins ties
        }
    }

    // Gather selected code row (float4 from L2) and scatter into [B,D,H,W].
    {
        const float4* c = reinterpret_cast<const float4*>(cb + bidx * DIMS);
        float* o = out + (size_t)b * (DIMS * HW) + hw;
        #pragma unroll
        for (int i = 0; i < DIMS / 4; ++i) {
            float4 v = c[i];
            o[(4 * i + 0) * HW] = v.x;
            o[(4 * i + 1) * HW] = v.y;
            o[(4 * i + 2) * HW] = v.z;
            o[(4 * i + 3) * HW] = v.w;
        }
    }

    // Per-thread min distance = ||x||^2 + score; deterministic block reduce.
    sRed[threadIdx.x] = xnorm + best;
    __syncthreads();
    #pragma unroll
    for (int s = THREADS / 2; s > 0; s >>= 1) {
        if (threadIdx.x < s) sRed[threadIdx.x] += sRed[threadIdx.x + s];
        __syncthreads();
    }
    if (threadIdx.x == 0) g_partial[blockIdx.x] = sRed[0];
}

// ---------------------------------------------------------------------------
// Final deterministic loss reduction: out[ndhw] = 1.25 * sum / (N*D)
// ---------------------------------------------------------------------------
__global__ void loss_kernel(float* __restrict__ out, int ndhw) {
    __shared__ float red[NBLOCKS];
    red[threadIdx.x] = g_partial[threadIdx.x];
    __syncthreads();
    #pragma unroll
    for (int s = NBLOCKS / 2; s > 0; s >>= 1) {
        if (threadIdx.x < s) red[threadIdx.x] += red[threadIdx.x + s];
        __syncthreads();
    }
    if (threadIdx.x == 0)
        out[ndhw] = 1.25f * red[0] / (float)ndhw;  // mean over B*H*W*D elements
}

// ---------------------------------------------------------------------------
extern "C" void kernel_launch(void* const* d_in, const int* in_sizes, int n_in,
                              void* d_out, int out_size) {
    const float* latents = (const float*)d_in[0];  // [64,64,32,32] = 4194304
    const float* cb      = (const float*)d_in[1];  // [1024,64]     = 65536
    float* out = (float*)d_out;                    // 4194304 quantized + 1 loss
    const int ndhw = in_sizes[0];                  // 4194304

    cnorm_kernel<<<(KCODES + 255) / 256, 256>>>(cb);
    vq_kernel<<<NBLOCKS, THREADS>>>(latents, cb, out);
    loss_kernel<<<1, NBLOCKS>>>(out, ndhw);
}

// round 4
// speedup vs baseline: 2.0393x; 1.8939x over previous
#include <cuda_runtime.h>
#include <cuda_bf16.h>
#include <cstdint>

// VectorQuantizer via mma.sync.m16n8k16 bf16 (non-'a' PTX -> HMMA on sm_103):
// 3-term bf16 split GEMM for distances, fused top-2 argmin, exact fp32 re-rank.
// latents [64,64,32,32] f32, codebook [1024,64] f32 ->
// out[0..4194303] = codebook[argmin], out[4194304] = 1.25*mean((q-x)^2).

#define DIMS    64
#define KCODES  1024
#define HW      1024
#define THREADS 128
#define NPOS    65536
#define NBLOCKS 512
#define PITCH   272                       // [hi 128B | lo 128B | pad 16B]
#define TILE_CODES 128
#define TILE_BYTES (TILE_CODES * PITCH)   // 34816

// smem layout (dynamic)
#define SM_A    0                         // 128 rows x 272B = 34816
#define SM_B0   34816
#define SM_B1   69632
#define SM_CN   104448                    // 1024 f32
#define SM_I1   108544                    // 128 int
#define SM_I2   109056                    // 128 int
#define SM_RED  109568                    // 128 f32
#define SM_TOTAL 110080

__device__ float g_cnorm[KCODES];
__device__ float g_partial[NBLOCKS];
__device__ __align__(16) unsigned char g_cb[KCODES * PITCH];

// ---------------- helpers ----------------
__device__ __forceinline__ uint32_t smem_u32(const void* p) {
    uint32_t a;
    asm("{ .reg .u64 t; cvta.to.shared.u64 t, %1; cvt.u32.u64 %0, t; }"
        : "=r"(a) : "l"(p));
    return a;
}

__device__ __forceinline__ uint32_t pack_bf16(float v0, float v1) {
    return (uint32_t)__bfloat16_as_ushort(__float2bfloat16(v0)) |
           ((uint32_t)__bfloat16_as_ushort(__float2bfloat16(v1)) << 16);
}

#define MMA(d, a, bb) \
    asm volatile("mma.sync.aligned.m16n8k16.row.col.f32.bf16.bf16.f32 " \
                 "{%0,%1,%2,%3}, {%4,%5,%6,%7}, {%8,%9}, {%0,%1,%2,%3};" \
                 : "+f"((d)[0]), "+f"((d)[1]), "+f"((d)[2]), "+f"((d)[3]) \
                 : "r"((a)[0]), "r"((a)[1]), "r"((a)[2]), "r"((a)[3]), \
                   "r"((bb)[0]), "r"((bb)[1]))

__device__ __forceinline__ void cpa16(uint32_t dst, const void* src) {
    asm volatile("cp.async.cg.shared.global [%0], [%1], 16;" :: "r"(dst), "l"(src));
}
#define CPA_COMMIT() asm volatile("cp.async.commit_group;" ::: "memory")
#define CPA_WAIT1()  asm volatile("cp.async.wait_group 1;" ::: "memory")

#define UPD(ri, s, ci) \
    do { if ((s) < best[ri]) { best2[ri] = best[ri]; i2[ri] = bidx[ri]; \
                               best[ri] = (s); bidx[ri] = (ci); } \
         else if ((s) < best2[ri]) { best2[ri] = (s); i2[ri] = (ci); } } while (0)

// ---------------------------------------------------------------------------
// Prep: codebook f32 -> packed [hi|lo] bf16 rows + exact ||c||^2 (round-1 order)
// ---------------------------------------------------------------------------
__global__ void prep_kernel(const float* __restrict__ cb) {
    int k = blockIdx.x * blockDim.x + threadIdx.x;
    if (k >= KCODES) return;
    const float* row = cb + k * DIMS;
    unsigned char* dst = g_cb + (size_t)k * PITCH;
    float s0 = 0.f, s1 = 0.f, s2 = 0.f, s3 = 0.f;
    #pragma unroll
    for (int d = 0; d < DIMS; d += 4) {
        float v0 = row[d], v1 = row[d + 1], v2 = row[d + 2], v3 = row[d + 3];
        s0 = fmaf(v0, v0, s0); s1 = fmaf(v1, v1, s1);
        s2 = fmaf(v2, v2, s2); s3 = fmaf(v3, v3, s3);
        __nv_bfloat16 h0 = __float2bfloat16(v0), h1 = __float2bfloat16(v1);
        __nv_bfloat16 h2 = __float2bfloat16(v2), h3 = __float2bfloat16(v3);
        *(uint32_t*)(dst + d * 2)     = (uint32_t)__bfloat16_as_ushort(h0) |
                                        ((uint32_t)__bfloat16_as_ushort(h1) << 16);
        *(uint32_t*)(dst + d * 2 + 4) = (uint32_t)__bfloat16_as_ushort(h2) |
                                        ((uint32_t)__bfloat16_as_ushort(h3) << 16);
        *(uint32_t*)(dst + 128 + d * 2) =
            pack_bf16(v0 - __bfloat162float(h0), v1 - __bfloat162float(h1));
        *(uint32_t*)(dst + 128 + d * 2 + 4) =
            pack_bf16(v2 - __bfloat162float(h2), v3 - __bfloat162float(h3));
    }
    g_cnorm[k] = (s0 + s1) + (s2 + s3);
}

// ---------------------------------------------------------------------------
// Main kernel
// ---------------------------------------------------------------------------
__global__ __launch_bounds__(THREADS) void vq_mma_kernel(
    const float* __restrict__ latents,
    const float* __restrict__ cb,
    float* __restrict__ out)
{
    extern __shared__ unsigned char smem[];
    const uint32_t sb = smem_u32(smem);
    const int tid  = threadIdx.x;
    const int w    = tid >> 5;
    const int lane = tid & 31;
    const int g    = lane >> 2;      // groupID
    const int c    = lane & 3;       // threadID_in_group

    // prefetch B tiles 0 and 1 (17 x 16B chunks per thread per tile)
    #pragma unroll
    for (int i = 0; i < 17; ++i)
        cpa16(sb + SM_B0 + tid * 16 + i * 2048, g_cb + tid * 16 + i * 2048);
    CPA_COMMIT();
    #pragma unroll
    for (int i = 0; i < 17; ++i)
        cpa16(sb + SM_B1 + tid * 16 + i * 2048,
              g_cb + TILE_BYTES + tid * 16 + i * 2048);
    CPA_COMMIT();

    // cnorm -> smem
    #pragma unroll
    for (int i = tid; i < KCODES; i += THREADS)
        ((float*)(smem + SM_CN))[i] = g_cnorm[i];

    // ---- build A row (this thread's position), hi|lo bf16, pitch 272 ----
    const int p  = blockIdx.x * THREADS + tid;
    const int b  = p >> 10;
    const int hw = p & (HW - 1);
    const float* xin = latents + (size_t)b * (DIMS * HW) + hw;
    unsigned char* arow = smem + SM_A + tid * PITCH;
    float xn0 = 0.f, xn1 = 0.f, xn2 = 0.f, xn3 = 0.f;
    #pragma unroll
    for (int d = 0; d < DIMS; d += 4) {
        float v0 = xin[(d + 0) * HW], v1 = xin[(d + 1) * HW];
        float v2 = xin[(d + 2) * HW], v3 = xin[(d + 3) * HW];
        xn0 = fmaf(v0, v0, xn0); xn1 = fmaf(v1, v1, xn1);
        xn2 = fmaf(v2, v2, xn2); xn3 = fmaf(v3, v3, xn3);
        __nv_bfloat16 h0 = __float2bfloat16(v0), h1 = __float2bfloat16(v1);
        __nv_bfloat16 h2 = __float2bfloat16(v2), h3 = __float2bfloat16(v3);
        *(uint32_t*)(arow + d * 2)     = (uint32_t)__bfloat16_as_ushort(h0) |
                                         ((uint32_t)__bfloat16_as_ushort(h1) << 16);
        *(uint32_t*)(arow + d * 2 + 4) = (uint32_t)__bfloat16_as_ushort(h2) |
                                         ((uint32_t)__bfloat16_as_ushort(h3) << 16);
        *(uint32_t*)(arow + 128 + d * 2) =
            pack_bf16(v0 - __bfloat162float(h0), v1 - __bfloat162float(h1));
        *(uint32_t*)(arow + 128 + d * 2 + 4) =
            pack_bf16(v2 - __bfloat162float(h2), v3 - __bfloat162float(h3));
    }
    const float xnorm = (xn0 + xn1) + (xn2 + xn3);
    __syncthreads();

    // ---- load A fragments (resident) ----
    // a0:(r,2c) a1:(r+8,2c) a2:(r,2c+8) a3:(r+8,2c+8); r = 32w+16mt+g, k-tile kt
    uint32_t aH[2][4][4], aL[2][4][4];
    const int rbase = 32 * w + g;
    #pragma unroll
    for (int mt = 0; mt < 2; ++mt)
        #pragma unroll
        for (int kt = 0; kt < 4; ++kt) {
            const unsigned char* base =
                smem + SM_A + (rbase + 16 * mt) * PITCH + 32 * kt + 4 * c;
            aH[mt][kt][0] = *(const uint32_t*)(base);
            aH[mt][kt][1] = *(const uint32_t*)(base + 8 * PITCH);
            aH[mt][kt][2] = *(const uint32_t*)(base + 16);
            aH[mt][kt][3] = *(const uint32_t*)(base + 8 * PITCH + 16);
            aL[mt][kt][0] = *(const uint32_t*)(base + 128);
            aL[mt][kt][1] = *(const uint32_t*)(base + 128 + 8 * PITCH);
            aL[mt][kt][2] = *(const uint32_t*)(base + 128 + 16);
            aL[mt][kt][3] = *(const uint32_t*)(base + 128 + 8 * PITCH + 16);
        }

    float best[4]  = {3.4e38f, 3.4e38f, 3.4e38f, 3.4e38f};
    float best2[4] = {3.4e38f, 3.4e38f, 3.4e38f, 3.4e38f};
    int   bidx[4]  = {0, 0, 0, 0};
    int   i2[4]    = {0, 0, 0, 0};

    #pragma unroll 1
    for (int tb = 0; tb < 8; ++tb) {
        CPA_WAIT1();
        __syncthreads();
        const unsigned char* bbuf = smem + SM_B0 + (tb & 1) * TILE_BYTES;

        #pragma unroll 1
        for (int np = 0; np < 8; ++np) {
            // B fragments for 2 n-tiles: b0 at (k=2c, n=g), b1 at k+8
            uint32_t bH[2][4][2], bL[2][4][2];
            #pragma unroll
            for (int j = 0; j < 2; ++j) {
                const unsigned char* rb =
                    bbuf + ((2 * np + j) * 8 + g) * PITCH + 4 * c;
                #pragma unroll
                for (int kt = 0; kt < 4; ++kt) {
                    bH[j][kt][0] = *(const uint32_t*)(rb + 32 * kt);
                    bH[j][kt][1] = *(const uint32_t*)(rb + 32 * kt + 16);
                    bL[j][kt][0] = *(const uint32_t*)(rb + 128 + 32 * kt);
                    bL[j][kt][1] = *(const uint32_t*)(rb + 128 + 32 * kt + 16);
                }
            }
            float D[2][2][4];
            #pragma unroll
            for (int j = 0; j < 2; ++j)
                #pragma unroll
                for (int mt = 0; mt < 2; ++mt)
                    #pragma unroll
                    for (int q = 0; q < 4; ++q) D[j][mt][q] = 0.f;

            #pragma unroll
            for (int kt = 0; kt < 4; ++kt) {
                MMA(D[0][0], aH[0][kt], bH[0][kt]);
                MMA(D[0][1], aH[1][kt], bH[0][kt]);
                MMA(D[1][0], aH[0][kt], bH[1][kt]);
                MMA(D[1][1], aH[1][kt], bH[1][kt]);
                MMA(D[0][0], aL[0][kt], bH[0][kt]);
                MMA(D[0][1], aL[1][kt], bH[0][kt]);
                MMA(D[1][0], aL[0][kt], bH[1][kt]);
                MMA(D[1][1], aL[1][kt], bH[1][kt]);
                MMA(D[0][0], aH[0][kt], bL[0][kt]);
                MMA(D[0][1], aH[1][kt], bL[0][kt]);
                MMA(D[1][0], aH[0][kt], bL[1][kt]);
                MMA(D[1][1], aH[1][kt], bL[1][kt]);
            }

            // epilogue: scores = cn - 2*dot; track per-row top-2
            #pragma unroll
            for (int j = 0; j < 2; ++j) {
                const int colb = tb * 128 + (2 * np + j) * 8 + 2 * c;
                const float2 cn2 = *(const float2*)(smem + SM_CN + colb * 4);
                #pragma unroll
                for (int mt = 0; mt < 2; ++mt) {
                    float s;
                    s = fmaf(-2.f, D[j][mt][0], cn2.x); UPD(2 * mt + 0, s, colb);
                    s = fmaf(-2.f, D[j][mt][1], cn2.y); UPD(2 * mt + 0, s, colb + 1);
                    s = fmaf(-2.f, D[j][mt][2], cn2.x); UPD(2 * mt + 1, s, colb);
                    s = fmaf(-2.f, D[j][mt][3], cn2.y); UPD(2 * mt + 1, s, colb + 1);
                }
            }
        }

        __syncthreads();   // everyone done reading buf[tb&1]
        if (tb + 2 < 8) {
            #pragma unroll
            for (int i = 0; i < 17; ++i)
                cpa16(sb + SM_B0 + (tb & 1) * TILE_BYTES + tid * 16 + i * 2048,
                      g_cb + (size_t)(tb + 2) * TILE_BYTES + tid * 16 + i * 2048);
        }
        CPA_COMMIT();      // empty group when no prefetch -> uniform accounting
    }

    // ---- merge top-2 across the 4 lanes (c) that share each row ----
    #pragma unroll
    for (int m = 1; m <= 2; m <<= 1) {
        #pragma unroll
        for (int r = 0; r < 4; ++r) {
            float ob  = __shfl_xor_sync(0xffffffffu, best[r], m);
            int   oi  = __shfl_xor_sync(0xffffffffu, bidx[r], m);
            float ob2 = __shfl_xor_sync(0xffffffffu, best2[r], m);
            int   oi2 = __shfl_xor_sync(0xffffffffu, i2[r], m);
            bool ow = (ob < best[r]) || (ob == best[r] && oi < bidx[r]);
            float nb  = ow ? ob : best[r];  int nbi = ow ? oi : bidx[r];
            float c1  = ow ? best[r] : ob;  int c1i = ow ? bidx[r] : oi;
            float c2  = ow ? ob2 : best2[r]; int c2i = ow ? oi2 : i2[r];
            bool s2 = (c2 < c1) || (c2 == c1 && c2i < c1i);
            best[r] = nb; bidx[r] = nbi;
            best2[r] = s2 ? c2 : c1; i2[r] = s2 ? c2i : c1i;
        }
    }
    int* sI1 = (int*)(smem + SM_I1);
    int* sI2 = (int*)(smem + SM_I2);
    if (c == 0) {
        #pragma unroll
        for (int r = 0; r < 4; ++r) {
            sI1[rbase + 8 * r] = bidx[r];
            sI2[rbase + 8 * r] = i2[r];
        }
    }
    __syncthreads();

    // ---- exact fp32 re-rank of the 2 candidates (round-1 accumulation order) ----
    const int cA = sI1[tid], cB = sI2[tid];
    const float4* pa = (const float4*)(cb + (size_t)cA * DIMS);
    const float4* pb = (const float4*)(cb + (size_t)cB * DIMS);
    float a0 = 0.f, a1 = 0.f, a2 = 0.f, a3 = 0.f;
    float b0 = 0.f, b1 = 0.f, b2 = 0.f, b3 = 0.f;
    #pragma unroll
    for (int d = 0; d < DIMS; d += 4) {
        float x0 = xin[(d + 0) * HW], x1 = xin[(d + 1) * HW];
        float x2 = xin[(d + 2) * HW], x3 = xin[(d + 3) * HW];
        float4 va = pa[d / 4], vb = pb[d / 4];
        a0 = fmaf(x0, va.x, a0); a1 = fmaf(x1, va.y, a1);
        a2 = fmaf(x2, va.z, a2); a3 = fmaf(x3, va.w, a3);
        b0 = fmaf(x0, vb.x, b0); b1 = fmaf(x1, vb.y, b1);
        b2 = fmaf(x2, vb.z, b2); b3 = fmaf(x3, vb.w, b3);
    }
    float sA = fmaf(-2.f, (a0 + a1) + (a2 + a3), g_cnorm[cA]);
    float sB = fmaf(-2.f, (b0 + b1) + (b2 + b3), g_cnorm[cB]);
    int   fin = cA;
    float fs  = sA;
    if (sB < sA || (sB == sA && cB < cA)) { fin = cB; fs = sB; }

    // ---- gather chosen code row, scatter to [B,D,H,W] ----
    {
        const float4* cc = (const float4*)(cb + (size_t)fin * DIMS);
        float* o = out + (size_t)b * (DIMS * HW) + hw;
        #pragma unroll
        for (int i = 0; i < DIMS / 4; ++i) {
            float4 v = cc[i];
            o[(4 * i + 0) * HW] = v.x;
            o[(4 * i + 1) * HW] = v.y;
            o[(4 * i + 2) * HW] = v.z;
            o[(4 * i + 3) * HW] = v.w;
        }
    }

    // ---- loss partial (deterministic block tree) ----
    float* red = (float*)(smem + SM_RED);
    red[tid] = xnorm + fs;
    __syncthreads();
    #pragma unroll
    for (int s = THREADS / 2; s > 0; s >>= 1) {
        if (tid < s) red[tid] += red[tid + s];
        __syncthreads();
    }
    if (tid == 0) g_partial[blockIdx.x] = red[0];
}

// ---------------------------------------------------------------------------
__global__ void loss_kernel(float* __restrict__ out, int ndhw) {
    __shared__ float red[NBLOCKS];
    red[threadIdx.x] = g_partial[threadIdx.x];
    __syncthreads();
    #pragma unroll
    for (int s = NBLOCKS / 2; s > 0; s >>= 1) {
        if (threadIdx.x < s) red[threadIdx.x] += red[threadIdx.x + s];
        __syncthreads();
    }
    if (threadIdx.x == 0)
        out[ndhw] = 1.25f * red[0] / (float)ndhw;
}

// ---------------------------------------------------------------------------
extern "C" void kernel_launch(void* const* d_in, const int* in_sizes, int n_in,
                              void* d_out, int out_size) {
    const float* latents = (const float*)d_in[0];  // [64,64,32,32]
    const float* cb      = (const float*)d_in[1];  // [1024,64]
    float* out = (float*)d_out;
    const int ndhw = in_sizes[0];                  // 4194304

    static int smem_set = 0;
    if (!smem_set) {
        cudaFuncSetAttribute(vq_mma_kernel,
                             cudaFuncAttributeMaxDynamicSharedMemorySize, SM_TOTAL);
        smem_set = 1;
    }

    prep_kernel<<<KCODES / 128, 128>>>(cb);
    vq_mma_kernel<<<NBLOCKS, THREADS, SM_TOTAL>>>(latents, cb, out);
    loss_kernel<<<1, NBLOCKS>>>(out, ndhw);
}